// round 11
// baseline (speedup 1.0000x reference)
#include <cuda_runtime.h>
#include <cuda_bf16.h>
#include <stdint.h>

// Problem constants (fixed shapes from setup_inputs)
#define B_SZ 32
#define C_SZ 512
#define T_PH 1024
#define TILE_T 1024       // frames per block tile
#define CPB    16         // channels per block
#define NT     256        // threads per block
#define NW     (NT / 32)  // warps per block

// -----------------------------------------------------------------------------
// Single fused kernel (R6 structure, binary search -> scatter table).
// Each block: (batch b, 1024-frame tile, 16-channel group).
//  1. Block-local inclusive scan of durations[b]; each thread keeps its 4
//     phones' frame ranges in registers.
//  2. Scatter phone indices into s_f2p for frames in this tile (zero-init
//     covers the invalid t >= total region; values are masked later anyway).
//  3. Single int4 LDS per thread for its 4 indices.
//  4. Gather x with a distance-2 channel software pipeline; float4 stores.
//  5. blockIdx.y==0 blocks also write the mel_mask tile.
// -----------------------------------------------------------------------------
__global__ void __launch_bounds__(NT, 5)
lr_fused_kernel(const float* __restrict__ x,
                const int* __restrict__ durations,
                float* __restrict__ out,
                float* __restrict__ mask,   // nullptr if no mask
                int M)
{
    const int b    = blockIdx.z;
    const int c0   = blockIdx.y * CPB;
    const int t0   = blockIdx.x * TILE_T;
    const int tid  = threadIdx.x;
    const int lane = tid & 31;
    const int wid  = tid >> 5;

    __shared__ int s_f2p[TILE_T];   // frame (tile-local) -> phone index
    __shared__ int s_wsum[NW];
    __shared__ int s_total;

    // zero-init scatter table (covers frames >= total; masked at store time)
    reinterpret_cast<int4*>(s_f2p)[tid] = make_int4(0, 0, 0, 0);

    // ---- 1. block scan of durations[b] (4 elements / thread) ----
    int4 dd = reinterpret_cast<const int4*>(durations + b * T_PH)[tid];
    const int s0 = dd.x;
    const int s1 = s0 + dd.y;
    const int s2 = s1 + dd.z;
    const int s3 = s2 + dd.w;

    int v = s3;                                   // thread sum
    #pragma unroll
    for (int off = 1; off < 32; off <<= 1) {
        int n = __shfl_up_sync(0xFFFFFFFFu, v, off);
        if (lane >= off) v += n;
    }
    if (lane == 31) s_wsum[wid] = v;
    __syncthreads();
    if (wid == 0) {
        int w = (lane < NW) ? s_wsum[lane] : 0;
        #pragma unroll
        for (int off = 1; off < NW; off <<= 1) {
            int n = __shfl_up_sync(0xFFFFFFFFu, w, off);
            if (lane >= off) w += n;
        }
        if (lane < NW) s_wsum[lane] = w;
    }
    __syncthreads();

    const int base = (wid ? s_wsum[wid - 1] : 0) + (v - s3);  // excl prefix
    if (tid == NT - 1) s_total = base + s3;

    // ---- 2. scatter: phone 4*tid+k covers frames [lo_k, hi_k) ----
    {
        const int ph  = tid * 4;
        const int lo[4] = { base,      base + s0, base + s1, base + s2 };
        const int hi[4] = { base + s0, base + s1, base + s2, base + s3 };
        #pragma unroll
        for (int k = 0; k < 4; ++k) {
            int a = lo[k] - t0;  if (a < 0) a = 0;
            int e = hi[k] - t0;  if (e > TILE_T) e = TILE_T;
            for (int t = a; t < e; ++t) s_f2p[t] = ph + k;
        }
    }
    __syncthreads();

    const int total = s_total;

    // ---- 5. mask tile (only one channel-group per (b, tile)) ----
    if (mask != nullptr && blockIdx.y == 0) {
        int tend = t0 + TILE_T; if (tend > M) tend = M;
        for (int t = t0 + tid; t < tend; t += NT)
            mask[b * M + t] = (t >= total) ? 1.0f : 0.0f;
    }

    const int tl = t0 + tid * 4;
    if (tl >= M) return;   // (M % 4 == 0 guaranteed by dispatch -> tl+3 < M)

    // ---- 3. one int4 LDS for this thread's 4 phone indices ----
    const int4 pp = reinterpret_cast<const int4*>(s_f2p)[tid];
    const int p0 = pp.x, p1 = pp.y, p2 = pp.z, p3 = pp.w;

    const float m0 = (tl + 0 < total) ? 1.0f : 0.0f;
    const float m1 = (tl + 1 < total) ? 1.0f : 0.0f;
    const float m2 = (tl + 2 < total) ? 1.0f : 0.0f;
    const float m3 = (tl + 3 < total) ? 1.0f : 0.0f;

    // ---- 4. gather: distance-2 channel software pipeline (32-bit offsets) ----
    const float* __restrict__ xb = x   + (b * C_SZ + c0) * T_PH;
    float*       __restrict__ ob = out + (b * C_SZ + c0) * M + tl;

    float a0, a1, a2, a3, e0, e1, e2, e3;
    {
        const float* __restrict__ xr0 = xb;
        const float* __restrict__ xr1 = xb + T_PH;
        a0 = __ldg(xr0 + p0); a1 = __ldg(xr0 + p1);
        a2 = __ldg(xr0 + p2); a3 = __ldg(xr0 + p3);
        e0 = __ldg(xr1 + p0); e1 = __ldg(xr1 + p1);
        e2 = __ldg(xr1 + p2); e3 = __ldg(xr1 + p3);
    }

    #pragma unroll
    for (int g = 0; g < CPB - 2; g += 2) {
        const float* __restrict__ xr0 = xb + (g + 2) * T_PH;
        const float* __restrict__ xr1 = xb + (g + 3) * T_PH;
        float n0 = __ldg(xr0 + p0), n1 = __ldg(xr0 + p1);
        float n2 = __ldg(xr0 + p2), n3 = __ldg(xr0 + p3);
        float q0 = __ldg(xr1 + p0), q1 = __ldg(xr1 + p1);
        float q2 = __ldg(xr1 + p2), q3 = __ldg(xr1 + p3);

        float4 oA = make_float4(a0 * m0, a1 * m1, a2 * m2, a3 * m3);
        float4 oE = make_float4(e0 * m0, e1 * m1, e2 * m2, e3 * m3);
        *reinterpret_cast<float4*>(ob + (g + 0) * M) = oA;
        *reinterpret_cast<float4*>(ob + (g + 1) * M) = oE;

        a0 = n0; a1 = n1; a2 = n2; a3 = n3;
        e0 = q0; e1 = q1; e2 = q2; e3 = q3;
    }

    {
        float4 oA = make_float4(a0 * m0, a1 * m1, a2 * m2, a3 * m3);
        float4 oE = make_float4(e0 * m0, e1 * m1, e2 * m2, e3 * m3);
        *reinterpret_cast<float4*>(ob + (CPB - 2) * M) = oA;
        *reinterpret_cast<float4*>(ob + (CPB - 1) * M) = oE;
    }
}

// -----------------------------------------------------------------------------
// Scalar fallback (only if M % 4 != 0) — fused, binary-search version.
// -----------------------------------------------------------------------------
__global__ void __launch_bounds__(NT)
lr_fused_scalar_kernel(const float* __restrict__ x,
                       const int* __restrict__ durations,
                       float* __restrict__ out,
                       float* __restrict__ mask,
                       int M)
{
    const int b    = blockIdx.z;
    const int c0   = blockIdx.y * CPB;
    const int t0   = blockIdx.x * NT;
    const int tid  = threadIdx.x;
    const int lane = tid & 31;
    const int wid  = tid >> 5;

    __shared__ int s_cum[T_PH];
    __shared__ int s_wsum[NW];

    int4 dd = reinterpret_cast<const int4*>(durations + b * T_PH)[tid];
    const int s0 = dd.x, s1 = s0 + dd.y, s2 = s1 + dd.z, s3 = s2 + dd.w;
    int v = s3;
    #pragma unroll
    for (int off = 1; off < 32; off <<= 1) {
        int n = __shfl_up_sync(0xFFFFFFFFu, v, off);
        if (lane >= off) v += n;
    }
    if (lane == 31) s_wsum[wid] = v;
    __syncthreads();
    if (wid == 0) {
        int w = (lane < NW) ? s_wsum[lane] : 0;
        #pragma unroll
        for (int off = 1; off < NW; off <<= 1) {
            int n = __shfl_up_sync(0xFFFFFFFFu, w, off);
            if (lane >= off) w += n;
        }
        if (lane < NW) s_wsum[lane] = w;
    }
    __syncthreads();
    const int base = (wid ? s_wsum[wid - 1] : 0) + (v - s3);
    reinterpret_cast<int4*>(s_cum)[tid] =
        make_int4(base + s0, base + s1, base + s2, base + s3);
    __syncthreads();

    const int total = s_cum[T_PH - 1];
    const int t = t0 + tid;

    if (mask != nullptr && blockIdx.y == 0 && t < M)
        mask[b * M + t] = (t >= total) ? 1.0f : 0.0f;

    if (t >= M) return;

    int p = 0;
    #pragma unroll
    for (int step = T_PH / 2; step > 0; step >>= 1)
        if (s_cum[p + step - 1] <= t) p += step;
    p = min(p, T_PH - 1);
    const bool val = (t < total);

    const float* xb = x + (b * C_SZ + c0) * T_PH;
    float* ob = out + (b * C_SZ + c0) * M + t;
    #pragma unroll
    for (int cc = 0; cc < CPB; ++cc)
        ob[cc * M] = val ? __ldg(xb + cc * T_PH + p) : 0.0f;
}

// -----------------------------------------------------------------------------
// Launch
// -----------------------------------------------------------------------------
extern "C" void kernel_launch(void* const* d_in, const int* in_sizes, int n_in,
                              void* d_out, int out_size)
{
    const float* x         = (const float*)d_in[0];
    const int*   durations = (const int*)d_in[1];
    float* out = (float*)d_out;

    // Resolve M and layout: tuple  out[B,C,M] ++ mask[B,M] => B*M*(C+1);
    // fallback out-only => B*M*C.
    long long os = (long long)out_size;
    int M;
    float* mask_ptr = nullptr;
    if (os % ((long long)B_SZ * (C_SZ + 1)) == 0) {
        M = (int)(os / ((long long)B_SZ * (C_SZ + 1)));
        mask_ptr = out + (size_t)B_SZ * C_SZ * M;
    } else {
        M = (int)(os / ((long long)B_SZ * C_SZ));
    }

    if ((M & 3) == 0) {
        dim3 grid((M + TILE_T - 1) / TILE_T, C_SZ / CPB, B_SZ);
        lr_fused_kernel<<<grid, NT>>>(x, durations, out, mask_ptr, M);
    } else {
        dim3 grid((M + NT - 1) / NT, C_SZ / CPB, B_SZ);
        lr_fused_scalar_kernel<<<grid, NT>>>(x, durations, out, mask_ptr, M);
    }
}

// round 12
// speedup vs baseline: 1.0660x; 1.0660x over previous
#include <cuda_runtime.h>
#include <cuda_bf16.h>
#include <stdint.h>

// Problem constants (fixed shapes from setup_inputs)
#define B_SZ 32
#define C_SZ 512
#define T_PH 1024
#define TILE_T 1024       // frames per block tile
#define CPB    16         // channels per block
#define NT     256        // threads per block
#define NW     (NT / 32)  // warps per block

// -----------------------------------------------------------------------------
// Single fused kernel (R6 configuration — measured best: 49.6us, HBM 5.1TB/s).
// Each block: (batch b, 1024-frame tile, 16-channel group).
//  1. Block-local inclusive scan of durations[b] (1024 ints) into smem.
//  2. Binary search this thread's 4 frames -> phone indices.
//  3. Gather x with a distance-2 channel software pipeline: loads for channels
//     {g+2,g+3} issue BEFORE the stores of {g,g+1}, hiding L2 latency.
//  4. blockIdx.y==0 blocks also write the mel_mask tile.
// __launch_bounds__(NT,5): 48 regs, 5 blocks/SM — measured optimum.
// -----------------------------------------------------------------------------
__global__ void __launch_bounds__(NT, 5)
lr_fused_kernel(const float* __restrict__ x,
                const int* __restrict__ durations,
                float* __restrict__ out,
                float* __restrict__ mask,   // nullptr if no mask
                int M)
{
    const int b    = blockIdx.z;
    const int c0   = blockIdx.y * CPB;
    const int t0   = blockIdx.x * TILE_T;
    const int tid  = threadIdx.x;
    const int lane = tid & 31;
    const int wid  = tid >> 5;

    __shared__ int s_cum[T_PH];
    __shared__ int s_wsum[NW];

    // ---- 1. block scan of durations[b] (4 elements / thread) ----
    int4 dd = reinterpret_cast<const int4*>(durations + b * T_PH)[tid];
    const int s0 = dd.x;
    const int s1 = s0 + dd.y;
    const int s2 = s1 + dd.z;
    const int s3 = s2 + dd.w;

    int v = s3;                                   // thread sum
    #pragma unroll
    for (int off = 1; off < 32; off <<= 1) {
        int n = __shfl_up_sync(0xFFFFFFFFu, v, off);
        if (lane >= off) v += n;
    }
    if (lane == 31) s_wsum[wid] = v;
    __syncthreads();
    if (wid == 0) {
        int w = (lane < NW) ? s_wsum[lane] : 0;
        #pragma unroll
        for (int off = 1; off < NW; off <<= 1) {
            int n = __shfl_up_sync(0xFFFFFFFFu, w, off);
            if (lane >= off) w += n;
        }
        if (lane < NW) s_wsum[lane] = w;
    }
    __syncthreads();

    const int base = (wid ? s_wsum[wid - 1] : 0) + (v - s3);
    reinterpret_cast<int4*>(s_cum)[tid] =
        make_int4(base + s0, base + s1, base + s2, base + s3);
    __syncthreads();

    const int total = s_cum[T_PH - 1];

    // ---- 4. mask tile (only one channel-group per (b, tile)) ----
    if (mask != nullptr && blockIdx.y == 0) {
        int tend = t0 + TILE_T; if (tend > M) tend = M;
        for (int t = t0 + tid; t < tend; t += NT)
            mask[(size_t)b * M + t] = (t >= total) ? 1.0f : 0.0f;
    }

    const int tl = t0 + tid * 4;
    if (tl >= M) return;   // (M % 4 == 0 guaranteed by dispatch -> tl+3 < M)

    // ---- 2. binary search: p = searchsorted(cum, t, 'right'), clipped ----
    int p0 = 0, p1 = 0, p2 = 0, p3 = 0;
    #pragma unroll
    for (int step = T_PH / 2; step > 0; step >>= 1) {
        if (s_cum[p0 + step - 1] <= tl + 0) p0 += step;
        if (s_cum[p1 + step - 1] <= tl + 1) p1 += step;
        if (s_cum[p2 + step - 1] <= tl + 2) p2 += step;
        if (s_cum[p3 + step - 1] <= tl + 3) p3 += step;
    }
    p0 = min(p0, T_PH - 1);
    p1 = min(p1, T_PH - 1);
    p2 = min(p2, T_PH - 1);
    p3 = min(p3, T_PH - 1);

    const float m0 = (tl + 0 < total) ? 1.0f : 0.0f;
    const float m1 = (tl + 1 < total) ? 1.0f : 0.0f;
    const float m2 = (tl + 2 < total) ? 1.0f : 0.0f;
    const float m3 = (tl + 3 < total) ? 1.0f : 0.0f;

    // ---- 3. gather: distance-2 channel software pipeline ----
    const float* __restrict__ xb = x   + ((size_t)(b * C_SZ + c0)) * T_PH;
    float*       __restrict__ ob = out + ((size_t)(b * C_SZ + c0)) * M + tl;

    // preload channels 0,1
    float a0, a1, a2, a3, e0, e1, e2, e3;
    {
        const float* __restrict__ xr0 = xb;
        const float* __restrict__ xr1 = xb + T_PH;
        a0 = __ldg(xr0 + p0); a1 = __ldg(xr0 + p1);
        a2 = __ldg(xr0 + p2); a3 = __ldg(xr0 + p3);
        e0 = __ldg(xr1 + p0); e1 = __ldg(xr1 + p1);
        e2 = __ldg(xr1 + p2); e3 = __ldg(xr1 + p3);
    }

    #pragma unroll
    for (int g = 0; g < CPB - 2; g += 2) {
        // issue next group's loads first
        const float* __restrict__ xr0 = xb + (size_t)(g + 2) * T_PH;
        const float* __restrict__ xr1 = xb + (size_t)(g + 3) * T_PH;
        float n0 = __ldg(xr0 + p0), n1 = __ldg(xr0 + p1);
        float n2 = __ldg(xr0 + p2), n3 = __ldg(xr0 + p3);
        float q0 = __ldg(xr1 + p0), q1 = __ldg(xr1 + p1);
        float q2 = __ldg(xr1 + p2), q3 = __ldg(xr1 + p3);

        // store current group
        float4 oA = make_float4(a0 * m0, a1 * m1, a2 * m2, a3 * m3);
        float4 oE = make_float4(e0 * m0, e1 * m1, e2 * m2, e3 * m3);
        *reinterpret_cast<float4*>(ob + (size_t)(g + 0) * M) = oA;
        *reinterpret_cast<float4*>(ob + (size_t)(g + 1) * M) = oE;

        a0 = n0; a1 = n1; a2 = n2; a3 = n3;
        e0 = q0; e1 = q1; e2 = q2; e3 = q3;
    }

    // epilogue: store last group
    {
        float4 oA = make_float4(a0 * m0, a1 * m1, a2 * m2, a3 * m3);
        float4 oE = make_float4(e0 * m0, e1 * m1, e2 * m2, e3 * m3);
        *reinterpret_cast<float4*>(ob + (size_t)(CPB - 2) * M) = oA;
        *reinterpret_cast<float4*>(ob + (size_t)(CPB - 1) * M) = oE;
    }
}

// -----------------------------------------------------------------------------
// Scalar fallback (only if M % 4 != 0) — same fused structure, 1 frame/thread.
// -----------------------------------------------------------------------------
__global__ void __launch_bounds__(NT)
lr_fused_scalar_kernel(const float* __restrict__ x,
                       const int* __restrict__ durations,
                       float* __restrict__ out,
                       float* __restrict__ mask,
                       int M)
{
    const int b    = blockIdx.z;
    const int c0   = blockIdx.y * CPB;
    const int t0   = blockIdx.x * NT;
    const int tid  = threadIdx.x;
    const int lane = tid & 31;
    const int wid  = tid >> 5;

    __shared__ int s_cum[T_PH];
    __shared__ int s_wsum[NW];

    int4 dd = reinterpret_cast<const int4*>(durations + b * T_PH)[tid];
    const int s0 = dd.x, s1 = s0 + dd.y, s2 = s1 + dd.z, s3 = s2 + dd.w;
    int v = s3;
    #pragma unroll
    for (int off = 1; off < 32; off <<= 1) {
        int n = __shfl_up_sync(0xFFFFFFFFu, v, off);
        if (lane >= off) v += n;
    }
    if (lane == 31) s_wsum[wid] = v;
    __syncthreads();
    if (wid == 0) {
        int w = (lane < NW) ? s_wsum[lane] : 0;
        #pragma unroll
        for (int off = 1; off < NW; off <<= 1) {
            int n = __shfl_up_sync(0xFFFFFFFFu, w, off);
            if (lane >= off) w += n;
        }
        if (lane < NW) s_wsum[lane] = w;
    }
    __syncthreads();
    const int base = (wid ? s_wsum[wid - 1] : 0) + (v - s3);
    reinterpret_cast<int4*>(s_cum)[tid] =
        make_int4(base + s0, base + s1, base + s2, base + s3);
    __syncthreads();

    const int total = s_cum[T_PH - 1];
    const int t = t0 + tid;

    if (mask != nullptr && blockIdx.y == 0 && t < M)
        mask[(size_t)b * M + t] = (t >= total) ? 1.0f : 0.0f;

    if (t >= M) return;

    int p = 0;
    #pragma unroll
    for (int step = T_PH / 2; step > 0; step >>= 1)
        if (s_cum[p + step - 1] <= t) p += step;
    p = min(p, T_PH - 1);
    const bool val = (t < total);

    const float* xb = x + ((size_t)(b * C_SZ + c0)) * T_PH;
    float* ob = out + ((size_t)(b * C_SZ + c0)) * M + t;
    #pragma unroll
    for (int cc = 0; cc < CPB; ++cc)
        ob[(size_t)cc * M] = val ? __ldg(xb + (size_t)cc * T_PH + p) : 0.0f;
}

// -----------------------------------------------------------------------------
// Launch
// -----------------------------------------------------------------------------
extern "C" void kernel_launch(void* const* d_in, const int* in_sizes, int n_in,
                              void* d_out, int out_size)
{
    const float* x         = (const float*)d_in[0];
    const int*   durations = (const int*)d_in[1];
    float* out = (float*)d_out;

    // Resolve M and layout: tuple  out[B,C,M] ++ mask[B,M] => B*M*(C+1);
    // fallback out-only => B*M*C.
    long long os = (long long)out_size;
    int M;
    float* mask_ptr = nullptr;
    if (os % ((long long)B_SZ * (C_SZ + 1)) == 0) {
        M = (int)(os / ((long long)B_SZ * (C_SZ + 1)));
        mask_ptr = out + (size_t)B_SZ * C_SZ * M;
    } else {
        M = (int)(os / ((long long)B_SZ * C_SZ));
    }

    if ((M & 3) == 0) {
        dim3 grid((M + TILE_T - 1) / TILE_T, C_SZ / CPB, B_SZ);
        lr_fused_kernel<<<grid, NT>>>(x, durations, out, mask_ptr, M);
    } else {
        dim3 grid((M + NT - 1) / NT, C_SZ / CPB, B_SZ);
        lr_fused_scalar_kernel<<<grid, NT>>>(x, durations, out, mask_ptr, M);
    }
}